// round 17
// baseline (speedup 1.0000x reference)
#include <cuda_runtime.h>
#include <math.h>

#define BB 16
#define NN 2048
#define MM 32
#define PP 48
#define TT 5
#define CC (PP*TT)   // 240

#define WPB 8            // warps (= atoms) per block
#define TH1 (WPB*32)     // 256 threads
#define NPB 4            // n-columns per norm block

// Per-atom BN partials: g_part[atom] = {sum, sumsq} over 240 channels.
// Unconditionally overwritten every launch -> deterministic, no zeroing.
__device__ float2 g_part[BB * NN];

__device__ __forceinline__ float ex2_fast(float x) {
    float r; asm("ex2.approx.f32 %0, %1;" : "=f"(r) : "f"(x)); return r;
}
__device__ __forceinline__ float sqrt_fast(float x) {
    float r; asm("sqrt.approx.f32 %0, %1;" : "=f"(r) : "f"(x)); return r;
}

// ---------------------------------------------------------------------------
// Kernel 1: warp-autonomous radial symmetry functions + BN partials.
// One warp per atom, zero __syncthreads:
//   1) lane = neighbor m: compute R, map Z -> type; ballot-compact the valid
//      (R,type) pairs into this warp's private smem row. __syncwarp only.
//   2) lane = radial index: slot0 p=lane, slot1 p=lane+32 (lane<16). Loop
//      over the warp-uniform count; rt[m] is a lane-invariant LDS broadcast;
//      element type t0 is warp-uniform so routing predicates never diverge.
//   3) coalesced stores op[k*48+p]; warp-reduced (s,s2) -> g_part[atom].
// ---------------------------------------------------------------------------
__global__ __launch_bounds__(TH1)
void rsf_kernel(const float* __restrict__ X,
                const float* __restrict__ rc,
                const float* __restrict__ rs,
                const float* __restrict__ re,
                const int*   __restrict__ Nbrs,
                const int*   __restrict__ NbrsZ,
                float*       __restrict__ out)
{
    __shared__ float2 sRT[WPB][MM];

    const int lane = threadIdx.x & 31;
    const int warp = threadIdx.x >> 5;
    const int atom = blockIdx.x * WPB + warp;   // atom = b*N + n
    const int b    = atom >> 11;

    // ---------- gather: lane = neighbor m ----------
    const float x0 = X[atom * 3 + 0];           // warp-uniform broadcast loads
    const float x1 = X[atom * 3 + 1];
    const float x2 = X[atom * 3 + 2];

    const int nb = Nbrs [atom * MM + lane];
    const int z  = NbrsZ[atom * MM + lane];
    const float* np_ = X + ((b << 11) + nb) * 3;
    const float dx = np_[0] - x0;
    const float dy = np_[1] - x1;
    const float dz = np_[2] - x2;
    const float R  = sqrt_fast(dx*dx + dy*dy + dz*dz);

    int t = -1;
    if      (z == 1)  t = 0;
    else if (z == 6)  t = 1;
    else if (z == 7)  t = 2;
    else if (z == 8)  t = 3;
    else if (z == 16) t = 4;

    const unsigned mask = __ballot_sync(0xffffffffu, t >= 0);
    const int cnt = __popc(mask);
    if (t >= 0) {
        const int pos = __popc(mask & ((1u << lane) - 1u));
        sRT[warp][pos] = make_float2(R, __int_as_float(t));
    }
    __syncwarp();

    // ---------- per-lane radial params (2 slots) ----------
    const int j1 = (lane < 16) ? (lane + 32) : lane;   // clamp; guarded later
    const float rc0 = rc[lane], rs0 = rs[lane];
    const float rc1 = rc[j1],   rs1 = rs[j1];
    const float ne0 = -re[lane] * 1.44269504088896f;
    const float ne1 = -re[j1]   * 1.44269504088896f;
    const float pc0 = 3.14159265358979f / rc0;
    const float pc1 = 3.14159265358979f / rc1;

    float a0[TT], a1[TT];
    #pragma unroll
    for (int k = 0; k < TT; k++) { a0[k] = 0.0f; a1[k] = 0.0f; }

    const float2* rt = sRT[warp];

    // ---------- main loop: warp-uniform trip count, unroll 2 ----------
    int m = 0;
    for (; m + 2 <= cnt; m += 2) {
        const float2 q0 = rt[m];        // lane-invariant address: broadcast
        const float2 q1 = rt[m + 1];
        const float Ra = q0.x, Rb = q1.x;
        const int   ta = __float_as_int(q0.y);   // warp-uniform
        const int   tb = __float_as_int(q1.y);

        // element a
        const float da0 = Ra - rs0, da1 = Ra - rs1;
        const float ea0 = ex2_fast(ne0 * da0 * da0);
        const float ea1 = ex2_fast(ne1 * da1 * da1);
        float fa0 = fmaf(__cosf(Ra * pc0), 0.5f, 0.5f);
        float fa1 = fmaf(__cosf(Ra * pc1), 0.5f, 0.5f);
        fa0 = (Ra <= rc0) ? fa0 : 0.0f;
        fa1 = (Ra <= rc1) ? fa1 : 0.0f;
        const float va0 = ea0 * fa0;
        const float va1 = ea1 * fa1;

        // element b
        const float db0 = Rb - rs0, db1 = Rb - rs1;
        const float eb0 = ex2_fast(ne0 * db0 * db0);
        const float eb1 = ex2_fast(ne1 * db1 * db1);
        float fb0 = fmaf(__cosf(Rb * pc0), 0.5f, 0.5f);
        float fb1 = fmaf(__cosf(Rb * pc1), 0.5f, 0.5f);
        fb0 = (Rb <= rc0) ? fb0 : 0.0f;
        fb1 = (Rb <= rc1) ? fb1 : 0.0f;
        const float vb0 = eb0 * fb0;
        const float vb1 = eb1 * fb1;

        #pragma unroll
        for (int k = 0; k < TT; k++) {
            if (ta == k) { a0[k] += va0; a1[k] += va1; }
            if (tb == k) { a0[k] += vb0; a1[k] += vb1; }
        }
    }
    if (m < cnt) {
        const float2 q0 = rt[m];
        const float Ra = q0.x;
        const int   ta = __float_as_int(q0.y);
        const float da0 = Ra - rs0, da1 = Ra - rs1;
        const float ea0 = ex2_fast(ne0 * da0 * da0);
        const float ea1 = ex2_fast(ne1 * da1 * da1);
        float fa0 = fmaf(__cosf(Ra * pc0), 0.5f, 0.5f);
        float fa1 = fmaf(__cosf(Ra * pc1), 0.5f, 0.5f);
        fa0 = (Ra <= rc0) ? fa0 : 0.0f;
        fa1 = (Ra <= rc1) ? fa1 : 0.0f;
        const float va0 = ea0 * fa0;
        const float va1 = ea1 * fa1;
        #pragma unroll
        for (int k = 0; k < TT; k++) {
            if (ta == k) { a0[k] += va0; a1[k] += va1; }
        }
    }

    // ---------- stores + BN stats ----------
    float s = 0.0f, s2 = 0.0f;
    float* op = out + (size_t)atom * CC;
    #pragma unroll
    for (int k = 0; k < TT; k++) {
        op[k * PP + lane] = a0[k];
        s  += a0[k];
        s2 = fmaf(a0[k], a0[k], s2);
        if (lane < 16) {
            op[k * PP + 32 + lane] = a1[k];
            s  += a1[k];
            s2 = fmaf(a1[k], a1[k], s2);
        }
    }

    #pragma unroll
    for (int o = 16; o > 0; o >>= 1) {
        s  += __shfl_down_sync(0xffffffffu, s,  o);
        s2 += __shfl_down_sync(0xffffffffu, s2, o);
    }
    if (lane == 0) g_part[atom] = make_float2(s, s2);
}

// ---------------------------------------------------------------------------
// Kernel 2: BatchNorm normalize (R14 version verbatim; measured ~12.5us).
// 512 blocks x 256; warps 0..3 compute stats for 4 n-columns in parallel,
// then all threads stream 4 x 960 float4.
// ---------------------------------------------------------------------------
__global__ __launch_bounds__(256)
void norm_kernel(float4* __restrict__ out4)
{
    const int n0  = blockIdx.x * NPB;
    const int tid = threadIdx.x;
    const int warp = tid >> 5;
    const int lane = tid & 31;

    __shared__ float2 sStat[NPB];    // {mean, inv} per n

    if (warp < NPB) {
        const int n = n0 + warp;
        float s = 0.0f, s2 = 0.0f;
        if (lane < BB) {
            const float2 p = g_part[lane * NN + n];
            s = p.x; s2 = p.y;
        }
        #pragma unroll
        for (int o = 16; o > 0; o >>= 1) {
            s  += __shfl_down_sync(0xffffffffu, s,  o);
            s2 += __shfl_down_sync(0xffffffffu, s2, o);
        }
        if (lane == 0) {
            const float invn = 1.0f / (float)(BB * CC);
            const float mean = s * invn;
            float var = s2 * invn - mean * mean;
            var = fmaxf(var, 0.0f);
            sStat[warp] = make_float2(mean, rsqrtf(var + 1e-5f));
        }
    }
    __syncthreads();

    #pragma unroll
    for (int nl = 0; nl < NPB; nl++) {
        const int n = n0 + nl;
        const float mean = sStat[nl].x;
        const float inv  = sStat[nl].y;

        float4 v[4];
        size_t idx[4];
        #pragma unroll
        for (int r = 0; r < 4; r++) {
            const int i = r * 256 + tid;
            if (i < 960) {
                const int b  = i / 60;
                const int c4 = i % 60;
                idx[r] = (size_t)(b * NN + n) * (CC / 4) + c4;
                v[r] = out4[idx[r]];
            }
        }
        #pragma unroll
        for (int r = 0; r < 4; r++) {
            const int i = r * 256 + tid;
            if (i < 960) {
                v[r].x = (v[r].x - mean) * inv;
                v[r].y = (v[r].y - mean) * inv;
                v[r].z = (v[r].z - mean) * inv;
                v[r].w = (v[r].w - mean) * inv;
                out4[idx[r]] = v[r];
            }
        }
    }
}

// ---------------------------------------------------------------------------
extern "C" void kernel_launch(void* const* d_in, const int* in_sizes, int n_in,
                              void* d_out, int out_size)
{
    const float* X     = (const float*)d_in[0];
    const float* rc    = (const float*)d_in[1];
    const float* rs    = (const float*)d_in[2];
    const float* re    = (const float*)d_in[3];
    const int*   Nbrs  = (const int*)  d_in[4];
    const int*   NbrsZ = (const int*)  d_in[5];

    const int nAtoms = BB * NN;                 // 32768
    rsf_kernel<<<nAtoms / WPB, TH1>>>(X, rc, rs, re, Nbrs, NbrsZ, (float*)d_out);
    norm_kernel<<<NN / NPB, 256>>>((float4*)d_out);
}